// round 1
// baseline (speedup 1.0000x reference)
#include <cuda_runtime.h>
#include <math.h>

#define T_  2048
#define D_  4096
#define H_  16
#define DH_ 256
#define RR_ 64
#define FF_ 16384

// ---------------- scratch (static device arrays: allocation-free) -----------
__device__ float g_xn  [(size_t)T_ * D_];
__device__ float g_q   [(size_t)T_ * D_];
__device__ float g_k   [(size_t)T_ * D_];
__device__ float g_v   [(size_t)T_ * D_];
__device__ float g_ctx [(size_t)T_ * D_];
__device__ float g_attn[(size_t)T_ * D_];
__device__ float g_h   [(size_t)T_ * FF_];
__device__ float g_sc  [(size_t)H_ * T_ * T_];   // 256 MB attention scores

// ---------------- LayerNorm --------------------------------------------------
__global__ void layernorm_kernel(const float* __restrict__ x,
                                 const float* __restrict__ scale,
                                 const float* __restrict__ offset,
                                 float* __restrict__ out)
{
    const int t = blockIdx.x;
    const float* xr = x + (size_t)t * D_;
    __shared__ float red[256];

    float s = 0.f;
    for (int i = threadIdx.x; i < D_; i += 256) s += xr[i];
    red[threadIdx.x] = s; __syncthreads();
    for (int o = 128; o > 0; o >>= 1) {
        if (threadIdx.x < o) red[threadIdx.x] += red[threadIdx.x + o];
        __syncthreads();
    }
    const float mean = red[0] * (1.0f / D_);
    __syncthreads();

    float vv = 0.f;
    for (int i = threadIdx.x; i < D_; i += 256) {
        float d = xr[i] - mean; vv += d * d;
    }
    red[threadIdx.x] = vv; __syncthreads();
    for (int o = 128; o > 0; o >>= 1) {
        if (threadIdx.x < o) red[threadIdx.x] += red[threadIdx.x + o];
        __syncthreads();
    }
    const float rstd = rsqrtf(red[0] * (1.0f / D_) + 1e-5f);

    float* orow = out + (size_t)t * D_;
    for (int i = threadIdx.x; i < D_; i += 256)
        orow[i] = (xr[i] - mean) * rstd * scale[i] + offset[i];
}

// ---------------- RoPE (in place on q and k) ---------------------------------
__global__ void rope_kernel(float* __restrict__ q, float* __restrict__ k)
{
    const int idx = blockIdx.x * blockDim.x + threadIdx.x;
    const int total = T_ * H_ * (RR_ / 2);
    if (idx >= total) return;
    const int i = idx % (RR_ / 2);
    const int h = (idx / (RR_ / 2)) % H_;
    const int t = idx / ((RR_ / 2) * H_);

    // angle in double for accuracy, cast like the fp32 reference
    const double inv = pow(10000.0, -2.0 * (double)i / (double)RR_);
    const double ang = (double)t * inv;
    const float c = (float)cos(ang);
    const float s = (float)sin(ang);

    const size_t base = (size_t)t * D_ + (size_t)h * DH_ + 2 * i;
    float qe = q[base], qo = q[base + 1];
    q[base]     = qe * c - qo * s;
    q[base + 1] = qo * c + qe * s;
    float ke = k[base], ko = k[base + 1];
    k[base]     = ke * c - ko * s;
    k[base + 1] = ko * c + ke * s;
}

// ---------------- Softmax over rows of scores --------------------------------
__global__ void softmax_kernel(float* __restrict__ scores)
{
    const size_t row = blockIdx.x;
    float* r = scores + row * (size_t)T_;
    __shared__ float red[256];

    float m = -1e30f;
    for (int i = threadIdx.x; i < T_; i += 256) m = fmaxf(m, r[i]);
    red[threadIdx.x] = m; __syncthreads();
    for (int o = 128; o > 0; o >>= 1) {
        if (threadIdx.x < o) red[threadIdx.x] = fmaxf(red[threadIdx.x], red[threadIdx.x + o]);
        __syncthreads();
    }
    m = red[0]; __syncthreads();

    float s = 0.f;
    for (int i = threadIdx.x; i < T_; i += 256) {
        float e = expf(r[i] - m);
        r[i] = e; s += e;
    }
    red[threadIdx.x] = s; __syncthreads();
    for (int o = 128; o > 0; o >>= 1) {
        if (threadIdx.x < o) red[threadIdx.x] += red[threadIdx.x + o];
        __syncthreads();
    }
    const float invs = 1.0f / red[0];
    for (int i = threadIdx.x; i < T_; i += 256) r[i] *= invs;
}

// ---------------- Generalized batched SGEMM ----------------------------------
// C[z][m][n] = alpha * sum_k A[z][m][k] * B[z][k][n]   (+ epilogue)
// A is row-major contiguous in k (element at A + m*lda + k).
// B element at B + k*bsk + n*bsn  (bsn==1 -> vectorized loads).
enum { EPI_NONE = 0, EPI_CAUSAL = 1, EPI_BIAS = 2, EPI_BIAS_GELU = 3, EPI_BIAS_RES = 4 };

__device__ __forceinline__ float gelu_f(float x)
{
    const float x3 = x * x * x;
    return 0.5f * x * (1.0f + tanhf(0.7978845608028654f * (x + 0.044715f * x3)));
}

__global__ __launch_bounds__(256)
void sgemm_kernel(int M, int N, int K,
                  const float* __restrict__ A, int lda, long long sA,
                  const float* __restrict__ B, int bsk, int bsn, long long sB,
                  float* __restrict__ C, int ldc, long long sC,
                  float alpha, int epi,
                  const float* __restrict__ bias,
                  const float* __restrict__ res, int ldres)
{
    A += (size_t)blockIdx.z * sA;
    B += (size_t)blockIdx.z * sB;
    C += (size_t)blockIdx.z * sC;

    const int m0 = blockIdx.y * 128;
    const int n0 = blockIdx.x * 128;

    __shared__ float As[8][128];
    __shared__ float Bs[8][128];

    const int tid = threadIdx.x;
    const int tx = tid & 15;        // 0..15  -> 8 cols each
    const int ty = tid >> 4;        // 0..15  -> 8 rows each

    float acc[8][8];
#pragma unroll
    for (int i = 0; i < 8; i++)
#pragma unroll
        for (int j = 0; j < 8; j++) acc[i][j] = 0.f;

    const int aRow = tid >> 1;          // 0..127
    const int aCol = (tid & 1) * 4;     // 0 or 4
    const int bRow = tid >> 5;          // 0..7
    const int bCol = (tid & 31) * 4;    // 0..124

    for (int k0 = 0; k0 < K; k0 += 8) {
        float4 av = *reinterpret_cast<const float4*>(
            A + (size_t)(m0 + aRow) * lda + (size_t)(k0 + aCol));
        As[aCol + 0][aRow] = av.x;
        As[aCol + 1][aRow] = av.y;
        As[aCol + 2][aRow] = av.z;
        As[aCol + 3][aRow] = av.w;

        if (bsn == 1) {
            float4 bv = *reinterpret_cast<const float4*>(
                B + (size_t)(k0 + bRow) * bsk + (size_t)(n0 + bCol));
            *reinterpret_cast<float4*>(&Bs[bRow][bCol]) = bv;
        } else {
#pragma unroll
            for (int j = 0; j < 4; j++)
                Bs[bRow][bCol + j] =
                    B[(size_t)(k0 + bRow) * bsk + (size_t)(n0 + bCol + j) * bsn];
        }
        __syncthreads();

#pragma unroll
        for (int kk = 0; kk < 8; kk++) {
            float ra[8], rb[8];
#pragma unroll
            for (int i = 0; i < 8; i++) ra[i] = As[kk][ty * 8 + i];
#pragma unroll
            for (int j = 0; j < 8; j++) rb[j] = Bs[kk][tx * 8 + j];
#pragma unroll
            for (int i = 0; i < 8; i++)
#pragma unroll
                for (int j = 0; j < 8; j++)
                    acc[i][j] += ra[i] * rb[j];
        }
        __syncthreads();
    }

    // epilogue
#pragma unroll
    for (int i = 0; i < 8; i++) {
        const int m = m0 + ty * 8 + i;
        float* crow = C + (size_t)m * ldc + (size_t)(n0 + tx * 8);
#pragma unroll
        for (int j = 0; j < 8; j++) {
            const int n = n0 + tx * 8 + j;
            float v = acc[i][j] * alpha;
            if (epi == EPI_CAUSAL) {
                if (n > m) v = -1e10f;
            } else if (epi == EPI_BIAS) {
                v += bias[n];
            } else if (epi == EPI_BIAS_GELU) {
                v = gelu_f(v + bias[n]);
            } else if (epi == EPI_BIAS_RES) {
                v += bias[n] + res[(size_t)m * ldres + n];
            }
            crow[j] = v;
        }
    }
}

// ---------------- launch -----------------------------------------------------
extern "C" void kernel_launch(void* const* d_in, const int* in_sizes, int n_in,
                              void* d_out, int out_size)
{
    const float* x    = (const float*)d_in[0];
    const float* ln_s = (const float*)d_in[1];
    const float* ln_o = (const float*)d_in[2];
    const float* wq   = (const float*)d_in[3];
    const float* wk   = (const float*)d_in[4];
    const float* wv   = (const float*)d_in[5];
    const float* wo   = (const float*)d_in[6];
    const float* w1   = (const float*)d_in[7];
    const float* b1   = (const float*)d_in[8];
    const float* w2   = (const float*)d_in[9];
    const float* b2   = (const float*)d_in[10];
    float* out = (float*)d_out;

    float *xn, *q, *k, *v, *ctx, *attn, *hbuf, *sc;
    cudaGetSymbolAddress((void**)&xn,   g_xn);
    cudaGetSymbolAddress((void**)&q,    g_q);
    cudaGetSymbolAddress((void**)&k,    g_k);
    cudaGetSymbolAddress((void**)&v,    g_v);
    cudaGetSymbolAddress((void**)&ctx,  g_ctx);
    cudaGetSymbolAddress((void**)&attn, g_attn);
    cudaGetSymbolAddress((void**)&hbuf, g_h);
    cudaGetSymbolAddress((void**)&sc,   g_sc);

    // 1) LayerNorm
    layernorm_kernel<<<T_, 256>>>(x, ln_s, ln_o, xn);

    // 2) Q/K/V projections: [2048,4096] @ [4096,4096]
    {
        dim3 g(D_ / 128, T_ / 128, 1);
        sgemm_kernel<<<g, 256>>>(T_, D_, D_, xn, D_, 0, wq, D_, 1, 0,
                                 q, D_, 0, 1.f, EPI_NONE, nullptr, nullptr, 0);
        sgemm_kernel<<<g, 256>>>(T_, D_, D_, xn, D_, 0, wk, D_, 1, 0,
                                 k, D_, 0, 1.f, EPI_NONE, nullptr, nullptr, 0);
        sgemm_kernel<<<g, 256>>>(T_, D_, D_, xn, D_, 0, wv, D_, 1, 0,
                                 v, D_, 0, 1.f, EPI_NONE, nullptr, nullptr, 0);
    }

    // 3) RoPE
    {
        const int total = T_ * H_ * (RR_ / 2);
        rope_kernel<<<(total + 255) / 256, 256>>>(q, k);
    }

    // 4) scores = scale * Q_h @ K_h^T  + causal mask  (batched over heads)
    {
        dim3 g(T_ / 128, T_ / 128, H_);
        // A = Q_h: base q + h*DH, lda = D;  B = K_h^T: element (d,s) at k[s*D + d]
        sgemm_kernel<<<g, 256>>>(T_, T_, DH_,
                                 q, D_, DH_,
                                 k, 1, D_, DH_,
                                 sc, T_, (long long)T_ * T_,
                                 0.0625f /* DH^-0.5 */, EPI_CAUSAL,
                                 nullptr, nullptr, 0);
    }

    // 5) softmax over each (h, t) row
    softmax_kernel<<<H_ * T_, 256>>>(sc);

    // 6) ctx = P_h @ V_h  (batched over heads)
    {
        dim3 g(DH_ / 128, T_ / 128, H_);
        sgemm_kernel<<<g, 256>>>(T_, DH_, T_,
                                 sc, T_, (long long)T_ * T_,
                                 v, D_, 1, DH_,
                                 ctx, D_, DH_,
                                 1.f, EPI_NONE, nullptr, nullptr, 0);
    }

    // 7) attn_out = ctx @ wo
    {
        dim3 g(D_ / 128, T_ / 128, 1);
        sgemm_kernel<<<g, 256>>>(T_, D_, D_, ctx, D_, 0, wo, D_, 1, 0,
                                 attn, D_, 0, 1.f, EPI_NONE, nullptr, nullptr, 0);
    }

    // 8) h = gelu(xn @ w1 + b1)
    {
        dim3 g(FF_ / 128, T_ / 128, 1);
        sgemm_kernel<<<g, 256>>>(T_, FF_, D_, xn, D_, 0, w1, FF_, 1, 0,
                                 hbuf, FF_, 0, 1.f, EPI_BIAS_GELU, b1, nullptr, 0);
    }

    // 9) out = h @ w2 + b2 + attn_out
    {
        dim3 g(D_ / 128, T_ / 128, 1);
        sgemm_kernel<<<g, 256>>>(T_, D_, FF_, hbuf, FF_, 0, w2, D_, 1, 0,
                                 out, D_, 0, 1.f, EPI_BIAS_RES, b2, attn, D_);
    }
}

// round 4
// speedup vs baseline: 2.2121x; 2.2121x over previous
#include <cuda_runtime.h>
#include <cuda_bf16.h>
#include <math.h>
#include <stdint.h>

#define T_  2048
#define D_  4096
#define H_  16
#define DH_ 256
#define RR_ 64
#define FF_ 16384

// GEMM tiling
#define MT   128
#define NTT  128
#define KC   32
#define STRIDE 80                 // smem bytes per 32-bf16 row (64B data + 16B pad)
#define STAGE  40960              // Ahi(10240)+Alo(10240)+Bhi(10240)+Blo(10240)
#define GEMM_SMEM_BYTES (2 * STAGE)

// ---------------- scratch (static device arrays: allocation-free) -----------
__device__ float g_xn  [(size_t)T_ * D_];
__device__ float g_q   [(size_t)T_ * D_];
__device__ float g_k   [(size_t)T_ * D_];
__device__ float g_v   [(size_t)T_ * D_];
__device__ float g_vt  [(size_t)H_ * DH_ * T_];
__device__ float g_ctx [(size_t)T_ * D_];
__device__ float g_attn[(size_t)T_ * D_];
__device__ float g_h   [(size_t)T_ * FF_];
__device__ float g_sc  [(size_t)H_ * T_ * T_];
__device__ float g_wqT [(size_t)D_ * D_];
__device__ float g_wkT [(size_t)D_ * D_];
__device__ float g_wvT [(size_t)D_ * D_];
__device__ float g_woT [(size_t)D_ * D_];
__device__ float g_w1T [(size_t)D_ * FF_];
__device__ float g_w2T [(size_t)D_ * FF_];

// ---------------- helpers ----------------------------------------------------
__device__ __forceinline__ uint32_t smem_u32(const void* p) {
    uint32_t a;
    asm("{ .reg .u64 t; cvta.to.shared.u64 t, %1; cvt.u32.u64 %0, t; }"
        : "=r"(a) : "l"(p));
    return a;
}

__device__ __forceinline__ void ldm_x4(uint32_t* r, uint32_t a) {
    asm volatile("ldmatrix.sync.aligned.m8n8.x4.shared.b16 {%0,%1,%2,%3}, [%4];"
                 : "=r"(r[0]), "=r"(r[1]), "=r"(r[2]), "=r"(r[3]) : "r"(a));
}

__device__ __forceinline__ void mma16816(float* d, const uint32_t* a, const uint32_t* b) {
    asm volatile("mma.sync.aligned.m16n8k16.row.col.f32.bf16.bf16.f32 "
                 "{%0,%1,%2,%3}, {%4,%5,%6,%7}, {%8,%9}, {%0,%1,%2,%3};"
                 : "+f"(d[0]), "+f"(d[1]), "+f"(d[2]), "+f"(d[3])
                 : "r"(a[0]), "r"(a[1]), "r"(a[2]), "r"(a[3]),
                   "r"(b[0]), "r"(b[1]));
}

// split fp32 pair -> packed bf16x2 hi and lo
__device__ __forceinline__ void split2(float x, float y, uint32_t& hi, uint32_t& lo) {
    __nv_bfloat16 hx = __float2bfloat16_rn(x);
    __nv_bfloat16 hy = __float2bfloat16_rn(y);
    float rx = x - __bfloat162float(hx);
    float ry = y - __bfloat162float(hy);
    __nv_bfloat16 lx = __float2bfloat16_rn(rx);
    __nv_bfloat16 ly = __float2bfloat16_rn(ry);
    hi = ((uint32_t)__bfloat16_as_ushort(hy) << 16) | (uint32_t)__bfloat16_as_ushort(hx);
    lo = ((uint32_t)__bfloat16_as_ushort(ly) << 16) | (uint32_t)__bfloat16_as_ushort(lx);
}

// ---------------- small kernels ---------------------------------------------
__global__ void layernorm_kernel(const float* __restrict__ x,
                                 const float* __restrict__ scale,
                                 const float* __restrict__ offset,
                                 float* __restrict__ out)
{
    const int t = blockIdx.x;
    const float* xr = x + (size_t)t * D_;
    __shared__ float red[256];

    float s = 0.f;
    for (int i = threadIdx.x; i < D_; i += 256) s += xr[i];
    red[threadIdx.x] = s; __syncthreads();
    for (int o = 128; o > 0; o >>= 1) {
        if (threadIdx.x < o) red[threadIdx.x] += red[threadIdx.x + o];
        __syncthreads();
    }
    const float mean = red[0] * (1.0f / D_);
    __syncthreads();

    float vv = 0.f;
    for (int i = threadIdx.x; i < D_; i += 256) {
        float d = xr[i] - mean; vv += d * d;
    }
    red[threadIdx.x] = vv; __syncthreads();
    for (int o = 128; o > 0; o >>= 1) {
        if (threadIdx.x < o) red[threadIdx.x] += red[threadIdx.x + o];
        __syncthreads();
    }
    const float rstd = rsqrtf(red[0] * (1.0f / D_) + 1e-5f);

    float* orow = out + (size_t)t * D_;
    for (int i = threadIdx.x; i < D_; i += 256)
        orow[i] = (xr[i] - mean) * rstd * scale[i] + offset[i];
}

__global__ void rope_kernel(float* __restrict__ q, float* __restrict__ k)
{
    const int idx = blockIdx.x * blockDim.x + threadIdx.x;
    const int total = T_ * H_ * (RR_ / 2);
    if (idx >= total) return;
    const int i = idx % (RR_ / 2);
    const int h = (idx / (RR_ / 2)) % H_;
    const int t = idx / ((RR_ / 2) * H_);

    const double inv = pow(10000.0, -2.0 * (double)i / (double)RR_);
    const double ang = (double)t * inv;
    const float c = (float)cos(ang);
    const float s = (float)sin(ang);

    const size_t base = (size_t)t * D_ + (size_t)h * DH_ + 2 * i;
    float qe = q[base], qo = q[base + 1];
    q[base]     = qe * c - qo * s;
    q[base + 1] = qo * c + qe * s;
    float ke = k[base], ko = k[base + 1];
    k[base]     = ke * c - ko * s;
    k[base + 1] = ko * c + ke * s;
}

__global__ void softmax_kernel(float* __restrict__ scores)
{
    const size_t row = blockIdx.x;
    float* r = scores + row * (size_t)T_;
    __shared__ float red[256];

    float m = -1e30f;
    for (int i = threadIdx.x; i < T_; i += 256) m = fmaxf(m, r[i]);
    red[threadIdx.x] = m; __syncthreads();
    for (int o = 128; o > 0; o >>= 1) {
        if (threadIdx.x < o) red[threadIdx.x] = fmaxf(red[threadIdx.x], red[threadIdx.x + o]);
        __syncthreads();
    }
    m = red[0]; __syncthreads();

    float s = 0.f;
    for (int i = threadIdx.x; i < T_; i += 256) {
        float e = __expf(r[i] - m);
        r[i] = e; s += e;
    }
    red[threadIdx.x] = s; __syncthreads();
    for (int o = 128; o > 0; o >>= 1) {
        if (threadIdx.x < o) red[threadIdx.x] += red[threadIdx.x + o];
        __syncthreads();
    }
    const float invs = 1.0f / red[0];
    for (int i = threadIdx.x; i < T_; i += 256) r[i] *= invs;
}

// transpose in[R][C] -> out[C][R]
__global__ void transpose_kernel(const float* __restrict__ in,
                                 float* __restrict__ out, int R, int C)
{
    __shared__ float t[32][33];
    const int c0 = blockIdx.x * 32, r0 = blockIdx.y * 32;
    const int x = threadIdx.x, y = threadIdx.y;
#pragma unroll
    for (int i = 0; i < 32; i += 8)
        t[y + i][x] = in[(size_t)(r0 + y + i) * C + c0 + x];
    __syncthreads();
#pragma unroll
    for (int i = 0; i < 32; i += 8)
        out[(size_t)(c0 + y + i) * R + r0 + x] = t[x][y + i];
}

// vt[h][d][t] = v[t][h*DH + d]
__global__ void transpose_v_kernel(const float* __restrict__ v,
                                   float* __restrict__ vt)
{
    __shared__ float s[32][33];
    const int h = blockIdx.z;
    const int d0 = blockIdx.x * 32, t0 = blockIdx.y * 32;
    const int x = threadIdx.x, y = threadIdx.y;
#pragma unroll
    for (int i = 0; i < 32; i += 8)
        s[y + i][x] = v[(size_t)(t0 + y + i) * D_ + (size_t)h * DH_ + d0 + x];
    __syncthreads();
#pragma unroll
    for (int i = 0; i < 32; i += 8)
        vt[((size_t)h * DH_ + d0 + y + i) * T_ + t0 + x] = s[x][y + i];
}

// ---------------- split-bf16 mma.sync GEMM -----------------------------------
// C[z][m][n] = alpha * sum_k A[z][m][k] * Bt[z][n][k]  (+ epilogue)
enum { EPI_NONE = 0, EPI_CAUSAL = 1, EPI_BIAS_GELU = 3, EPI_BIAS_RES = 4 };

__device__ __forceinline__ float gelu_f(float x)
{
    const float x3 = x * x * x;
    return 0.5f * x * (1.0f + tanhf(0.7978845608028654f * (x + 0.044715f * x3)));
}

__global__ void __launch_bounds__(256)
mma_gemm(int K,
         const float* __restrict__ A, int lda, long long sA,
         const float* __restrict__ Bt, int ldb, long long sB,
         float* __restrict__ C, int ldc, long long sC,
         float alpha, int epi,
         const float* __restrict__ bias,
         const float* __restrict__ res, int ldres)
{
    extern __shared__ char smem[];
    const uint32_t sbase = smem_u32(smem);
    const int tid = threadIdx.x;
    const int wid = tid >> 5, lid = tid & 31;
    const int m0 = blockIdx.y * MT, n0 = blockIdx.x * NTT;

    A  += (size_t)blockIdx.z * sA;
    Bt += (size_t)blockIdx.z * sB;
    C  += (size_t)blockIdx.z * sC;

    // fully-masked causal tile: write mask, skip compute
    if (epi == EPI_CAUSAL && n0 > m0 + (MT - 1)) {
        for (int idx = tid * 4; idx < MT * NTT; idx += 256 * 4) {
            const int r = idx / NTT, cc = idx % NTT;
            float4 mv = make_float4(-1e10f, -1e10f, -1e10f, -1e10f);
            *reinterpret_cast<float4*>(C + (size_t)(m0 + r) * ldc + n0 + cc) = mv;
        }
        return;
    }

    // warp layout: 2 m-bands x 4 n-cols
    const int wm = (wid >> 2) * 64;
    const int wn = (wid & 3) * 32;

    float acc[4][4][4];
#pragma unroll
    for (int i = 0; i < 4; i++)
#pragma unroll
        for (int j = 0; j < 4; j++)
#pragma unroll
            for (int r = 0; r < 4; r++) acc[i][j][r] = 0.f;

    // per-thread gmem load setup: row = tid>>1 (128 rows), half = tid&1 (16 floats)
    const int grow = tid >> 1, ghalf = tid & 1;
    const float* Aptr = A + (size_t)(m0 + grow) * lda + ghalf * 16;
    const float* Bptr = Bt + (size_t)(n0 + grow) * ldb + ghalf * 16;
    const uint32_t stRow = (uint32_t)grow * STRIDE + (uint32_t)ghalf * 32;

    // ldmatrix address bases (relative to tile start)
    const uint32_t aOff = (uint32_t)((wm + (lid & 15)) * STRIDE + (lid >> 4) * 16);
    const uint32_t bOff = (uint32_t)((wn + (lid & 7) + ((lid >> 4) << 3)) * STRIDE
                                     + (((lid >> 3) & 1) << 4));

    const int NC = K / KC;
    float4 pa[4], pb[4];

    // prologue: stage 0
#pragma unroll
    for (int i = 0; i < 4; i++) {
        pa[i] = *reinterpret_cast<const float4*>(Aptr + i * 4);
        pb[i] = *reinterpret_cast<const float4*>(Bptr + i * 4);
    }
#pragma unroll
    for (int i = 0; i < 4; i++) {
        uint32_t h0, l0, h1, l1;
        split2(pa[i].x, pa[i].y, h0, l0);
        split2(pa[i].z, pa[i].w, h1, l1);
        *reinterpret_cast<uint2*>(smem + stRow + i * 8)         = make_uint2(h0, h1);
        *reinterpret_cast<uint2*>(smem + 10240 + stRow + i * 8) = make_uint2(l0, l1);
        split2(pb[i].x, pb[i].y, h0, l0);
        split2(pb[i].z, pb[i].w, h1, l1);
        *reinterpret_cast<uint2*>(smem + 20480 + stRow + i * 8) = make_uint2(h0, h1);
        *reinterpret_cast<uint2*>(smem + 30720 + stRow + i * 8) = make_uint2(l0, l1);
    }
    __syncthreads();

    for (int c = 0; c < NC; ++c) {
        const int s = c & 1;
        if (c + 1 < NC) {
            const int kn = (c + 1) * KC;
#pragma unroll
            for (int i = 0; i < 4; i++) {
                pa[i] = *reinterpret_cast<const float4*>(Aptr + kn + i * 4);
                pb[i] = *reinterpret_cast<const float4*>(Bptr + kn + i * 4);
            }
        }

        const uint32_t st = sbase + (uint32_t)s * STAGE;
        const uint32_t aHi = st, aLo = st + 10240, bHi = st + 20480, bLo = st + 30720;

#pragma unroll
        for (int ks = 0; ks < 2; ks++) {
            const uint32_t kb = (uint32_t)ks * 32;
            uint32_t ah[4][4], al[4][4], bh[4][2], bl[4][2];
#pragma unroll
            for (int i = 0; i < 4; i++) {
                ldm_x4(ah[i], aHi + aOff + (uint32_t)i * (16 * STRIDE) + kb);
                ldm_x4(al[i], aLo + aOff + (uint32_t)i * (16 * STRIDE) + kb);
            }
#pragma unroll
            for (int j = 0; j < 2; j++) {
                uint32_t t4[4];
                ldm_x4(t4, bHi + bOff + (uint32_t)j * (16 * STRIDE) + kb);
                bh[2 * j][0] = t4[0]; bh[2 * j][1] = t4[1];
                bh[2 * j + 1][0] = t4[2]; bh[2 * j + 1][1] = t4[3];
                ldm_x4(t4, bLo + bOff + (uint32_t)j * (16 * STRIDE) + kb);
                bl[2 * j][0] = t4[0]; bl[2 * j][1] = t4[1];
                bl[2 * j + 1][0] = t4[2]; bl[2 * j + 1][1] = t4[3];
            }
#pragma unroll
            for (int i = 0; i < 4; i++)
#pragma unroll
                for (int j = 0; j < 4; j++) {
                    mma16816(acc[i][j], ah[i], bh[j]);
                    mma16816(acc[i][j], ah[i], bl[j]);
                    mma16816(acc[i][j], al[i], bh[j]);
                }
        }

        if (c + 1 < NC) {
            char* dst = smem + (size_t)(1 - s) * STAGE;
#pragma unroll
            for (int i = 0; i < 4; i++) {
                uint32_t h0, l0, h1, l1;
                split2(pa[i].x, pa[i].y, h0, l0);
                split2(pa[i].z, pa[i].w, h1, l1);
                *reinterpret_cast<uint2*>(dst + stRow + i * 8)         = make_uint2(h0, h1);
                *reinterpret_cast<uint2*>(dst + 10240 + stRow + i * 8) = make_uint2(l0, l1);
                split2(pb[i].x, pb[i].y, h0, l0);
                split2(pb[i].z, pb[i].w, h1, l1);
                *reinterpret_cast<uint2*>(dst + 20480 + stRow + i * 8) = make_uint2(h0, h1);
                *reinterpret_cast<uint2*>(dst + 30720 + stRow + i * 8) = make_uint2(l0, l1);
            }
        }
        __syncthreads();
    }

    // ---------------- epilogue ----------------
    const int tr = lid >> 2, tc = (lid & 3) * 2;
#pragma unroll
    for (int i = 0; i < 4; i++) {
        const int m1 = m0 + wm + i * 16 + tr;
        const int m2 = m1 + 8;
#pragma unroll
        for (int j = 0; j < 4; j++) {
            const int n = n0 + wn + j * 8 + tc;
            float v0 = acc[i][j][0] * alpha;
            float v1 = acc[i][j][1] * alpha;
            float v2 = acc[i][j][2] * alpha;
            float v3 = acc[i][j][3] * alpha;
            if (epi == EPI_CAUSAL) {
                if (n     > m1) v0 = -1e10f;
                if (n + 1 > m1) v1 = -1e10f;
                if (n     > m2) v2 = -1e10f;
                if (n + 1 > m2) v3 = -1e10f;
            } else if (epi == EPI_BIAS_GELU) {
                const float b0 = bias[n], b1 = bias[n + 1];
                v0 = gelu_f(v0 + b0); v1 = gelu_f(v1 + b1);
                v2 = gelu_f(v2 + b0); v3 = gelu_f(v3 + b1);
            } else if (epi == EPI_BIAS_RES) {
                const float b0 = bias[n], b1 = bias[n + 1];
                const float2 r1 = *reinterpret_cast<const float2*>(res + (size_t)m1 * ldres + n);
                const float2 r2 = *reinterpret_cast<const float2*>(res + (size_t)m2 * ldres + n);
                v0 += b0 + r1.x; v1 += b1 + r1.y;
                v2 += b0 + r2.x; v3 += b1 + r2.y;
            }
            *reinterpret_cast<float2*>(C + (size_t)m1 * ldc + n) = make_float2(v0, v1);
            *reinterpret_cast<float2*>(C + (size_t)m2 * ldc + n) = make_float2(v2, v3);
        }
    }
}

// ---------------- launch -----------------------------------------------------
extern "C" void kernel_launch(void* const* d_in, const int* in_sizes, int n_in,
                              void* d_out, int out_size)
{
    const float* x    = (const float*)d_in[0];
    const float* ln_s = (const float*)d_in[1];
    const float* ln_o = (const float*)d_in[2];
    const float* wq   = (const float*)d_in[3];
    const float* wk   = (const float*)d_in[4];
    const float* wv   = (const float*)d_in[5];
    const float* wo   = (const float*)d_in[6];
    const float* w1   = (const float*)d_in[7];
    const float* b1   = (const float*)d_in[8];
    const float* w2   = (const float*)d_in[9];
    const float* b2   = (const float*)d_in[10];
    float* out = (float*)d_out;

    float *xn, *q, *k, *v, *vt, *ctx, *attn, *hbuf, *sc;
    float *wqT, *wkT, *wvT, *woT, *w1T, *w2T;
    cudaGetSymbolAddress((void**)&xn,   g_xn);
    cudaGetSymbolAddress((void**)&q,    g_q);
    cudaGetSymbolAddress((void**)&k,    g_k);
    cudaGetSymbolAddress((void**)&v,    g_v);
    cudaGetSymbolAddress((void**)&vt,   g_vt);
    cudaGetSymbolAddress((void**)&ctx,  g_ctx);
    cudaGetSymbolAddress((void**)&attn, g_attn);
    cudaGetSymbolAddress((void**)&hbuf, g_h);
    cudaGetSymbolAddress((void**)&sc,   g_sc);
    cudaGetSymbolAddress((void**)&wqT,  g_wqT);
    cudaGetSymbolAddress((void**)&wkT,  g_wkT);
    cudaGetSymbolAddress((void**)&wvT,  g_wvT);
    cudaGetSymbolAddress((void**)&woT,  g_woT);
    cudaGetSymbolAddress((void**)&w1T,  g_w1T);
    cudaGetSymbolAddress((void**)&w2T,  g_w2T);

    cudaFuncSetAttribute(mma_gemm, cudaFuncAttributeMaxDynamicSharedMemorySize,
                         GEMM_SMEM_BYTES);

    const dim3 tb32(32, 8);

    // 0) weight transposes (W[k][n] -> WT[n][k], fp32)
    transpose_kernel<<<dim3(D_ / 32, D_ / 32), tb32>>>(wq, wqT, D_, D_);
    transpose_kernel<<<dim3(D_ / 32, D_ / 32), tb32>>>(wk, wkT, D_, D_);
    transpose_kernel<<<dim3(D_ / 32, D_ / 32), tb32>>>(wv, wvT, D_, D_);
    transpose_kernel<<<dim3(D_ / 32, D_ / 32), tb32>>>(wo, woT, D_, D_);
    transpose_kernel<<<dim3(FF_ / 32, D_ / 32), tb32>>>(w1, w1T, D_, FF_);
    transpose_kernel<<<dim3(D_ / 32, FF_ / 32), tb32>>>(w2, w2T, FF_, D_);

    // 1) LayerNorm
    layernorm_kernel<<<T_, 256>>>(x, ln_s, ln_o, xn);

    // 2) Q/K/V projections
    {
        dim3 g(D_ / NTT, T_ / MT, 1);
        mma_gemm<<<g, 256, GEMM_SMEM_BYTES>>>(D_, xn, D_, 0, wqT, D_, 0,
                                              q, D_, 0, 1.f, EPI_NONE, nullptr, nullptr, 0);
        mma_gemm<<<g, 256, GEMM_SMEM_BYTES>>>(D_, xn, D_, 0, wkT, D_, 0,
                                              k, D_, 0, 1.f, EPI_NONE, nullptr, nullptr, 0);
        mma_gemm<<<g, 256, GEMM_SMEM_BYTES>>>(D_, xn, D_, 0, wvT, D_, 0,
                                              v, D_, 0, 1.f, EPI_NONE, nullptr, nullptr, 0);
    }

    // 3) RoPE
    {
        const int total = T_ * H_ * (RR_ / 2);
        rope_kernel<<<(total + 255) / 256, 256>>>(q, k);
    }

    // 4) V transpose per head
    transpose_v_kernel<<<dim3(DH_ / 32, T_ / 32, H_), tb32>>>(v, vt);

    // 5) scores = scale * Q_h @ K_h^T + causal
    {
        dim3 g(T_ / NTT, T_ / MT, H_);
        mma_gemm<<<g, 256, GEMM_SMEM_BYTES>>>(DH_,
            q, D_, DH_,
            k, D_, DH_,
            sc, T_, (long long)T_ * T_,
            0.0625f, EPI_CAUSAL, nullptr, nullptr, 0);
    }

    // 6) softmax
    softmax_kernel<<<H_ * T_, 256>>>(sc);

    // 7) ctx = P_h @ V_h
    {
        dim3 g(DH_ / NTT, T_ / MT, H_);
        mma_gemm<<<g, 256, GEMM_SMEM_BYTES>>>(T_,
            sc, T_, (long long)T_ * T_,
            vt, T_, (long long)DH_ * T_,
            ctx, D_, DH_,
            1.f, EPI_NONE, nullptr, nullptr, 0);
    }

    // 8) attn_out = ctx @ wo
    {
        dim3 g(D_ / NTT, T_ / MT, 1);
        mma_gemm<<<g, 256, GEMM_SMEM_BYTES>>>(D_, ctx, D_, 0, woT, D_, 0,
                                              attn, D_, 0, 1.f, EPI_NONE, nullptr, nullptr, 0);
    }

    // 9) h = gelu(xn @ w1 + b1)
    {
        dim3 g(FF_ / NTT, T_ / MT, 1);
        mma_gemm<<<g, 256, GEMM_SMEM_BYTES>>>(D_, xn, D_, 0, w1T, D_, 0,
                                              hbuf, FF_, 0, 1.f, EPI_BIAS_GELU, b1, nullptr, 0);
    }

    // 10) out = h @ w2 + b2 + attn_out
    {
        dim3 g(D_ / NTT, T_ / MT, 1);
        mma_gemm<<<g, 256, GEMM_SMEM_BYTES>>>(FF_, hbuf, FF_, 0, w2T, FF_, 0,
                                              out, D_, 0, 1.f, EPI_BIAS_RES, b2, attn, D_);
    }
}

// round 5
// speedup vs baseline: 3.2283x; 1.4594x over previous
#include <cuda_runtime.h>
#include <cuda_bf16.h>
#include <math.h>
#include <stdint.h>

#define T_  2048
#define D_  4096
#define H_  16
#define DH_ 256
#define RR_ 64
#define FF_ 16384

// GEMM tiling
#define MT   128
#define NTT  128
#define KC   64
#define STAGE_B 65536            // Ah(16K)+Al(16K)+Bh(16K)+Bl(16K)
#define NSTAGE 3
#define GEMM_SMEM_BYTES (NSTAGE * STAGE_B)

typedef __nv_bfloat16 bf16;

// ---------------- scratch (static device arrays: allocation-free) -----------
__device__ float g_q   [(size_t)T_ * D_];
__device__ float g_k   [(size_t)T_ * D_];
__device__ float g_v   [(size_t)T_ * D_];
__device__ float g_attn[(size_t)T_ * D_];
__device__ float g_sc  [(size_t)H_ * T_ * T_];

__device__ bf16 g_xnh [(size_t)T_ * D_];
__device__ bf16 g_xnl [(size_t)T_ * D_];
__device__ bf16 g_qh  [(size_t)T_ * D_];
__device__ bf16 g_ql  [(size_t)T_ * D_];
__device__ bf16 g_kh  [(size_t)T_ * D_];
__device__ bf16 g_kl  [(size_t)T_ * D_];
__device__ bf16 g_vth [(size_t)H_ * DH_ * T_];
__device__ bf16 g_vtl [(size_t)H_ * DH_ * T_];
__device__ bf16 g_sch [(size_t)H_ * T_ * T_];
__device__ bf16 g_scl [(size_t)H_ * T_ * T_];
__device__ bf16 g_cxh [(size_t)T_ * D_];
__device__ bf16 g_cxl [(size_t)T_ * D_];
__device__ bf16 g_hbh [(size_t)T_ * FF_];
__device__ bf16 g_hbl [(size_t)T_ * FF_];
__device__ bf16 g_wqh [(size_t)D_ * D_];
__device__ bf16 g_wql [(size_t)D_ * D_];
__device__ bf16 g_wkh [(size_t)D_ * D_];
__device__ bf16 g_wkl [(size_t)D_ * D_];
__device__ bf16 g_wvh [(size_t)D_ * D_];
__device__ bf16 g_wvl [(size_t)D_ * D_];
__device__ bf16 g_woh [(size_t)D_ * D_];
__device__ bf16 g_wol [(size_t)D_ * D_];
__device__ bf16 g_w1h [(size_t)D_ * FF_];
__device__ bf16 g_w1l [(size_t)D_ * FF_];
__device__ bf16 g_w2h [(size_t)D_ * FF_];
__device__ bf16 g_w2l [(size_t)D_ * FF_];

// ---------------- helpers ----------------------------------------------------
__device__ __forceinline__ uint32_t smem_u32(const void* p) {
    uint32_t a;
    asm("{ .reg .u64 t; cvta.to.shared.u64 t, %1; cvt.u32.u64 %0, t; }"
        : "=r"(a) : "l"(p));
    return a;
}

#define SWZ(o) ((o) ^ (((o) >> 3) & 0x70))

#define CP16(dst, src) \
    asm volatile("cp.async.cg.shared.global [%0], [%1], 16;" \
                 :: "r"(dst), "l"(src))
#define CPCOMMIT() asm volatile("cp.async.commit_group;" ::: "memory")
#define CPWAIT(n)  asm volatile("cp.async.wait_group %0;" :: "n"(n) : "memory")

__device__ __forceinline__ void ldm_x4(uint32_t* r, uint32_t a) {
    asm volatile("ldmatrix.sync.aligned.m8n8.x4.shared.b16 {%0,%1,%2,%3}, [%4];"
                 : "=r"(r[0]), "=r"(r[1]), "=r"(r[2]), "=r"(r[3]) : "r"(a));
}

__device__ __forceinline__ void mma16816(float* d, const uint32_t* a, const uint32_t* b) {
    asm volatile("mma.sync.aligned.m16n8k16.row.col.f32.bf16.bf16.f32 "
                 "{%0,%1,%2,%3}, {%4,%5,%6,%7}, {%8,%9}, {%0,%1,%2,%3};"
                 : "+f"(d[0]), "+f"(d[1]), "+f"(d[2]), "+f"(d[3])
                 : "r"(a[0]), "r"(a[1]), "r"(a[2]), "r"(a[3]),
                   "r"(b[0]), "r"(b[1]));
}

// split fp32 pair -> packed bf16x2 hi and lo
__device__ __forceinline__ void split2(float x, float y, uint32_t& hi, uint32_t& lo) {
    bf16 hx = __float2bfloat16_rn(x);
    bf16 hy = __float2bfloat16_rn(y);
    float rx = x - __bfloat162float(hx);
    float ry = y - __bfloat162float(hy);
    bf16 lx = __float2bfloat16_rn(rx);
    bf16 ly = __float2bfloat16_rn(ry);
    hi = ((uint32_t)__bfloat16_as_ushort(hy) << 16) | (uint32_t)__bfloat16_as_ushort(hx);
    lo = ((uint32_t)__bfloat16_as_ushort(ly) << 16) | (uint32_t)__bfloat16_as_ushort(lx);
}

__device__ __forceinline__ float gelu_f(float x)
{
    const float x3 = x * x * x;
    return 0.5f * x * (1.0f + tanhf(0.7978845608028654f * (x + 0.044715f * x3)));
}

// ---------------- LayerNorm -> split bf16 ------------------------------------
__global__ void ln_split_kernel(const float* __restrict__ x,
                                const float* __restrict__ scale,
                                const float* __restrict__ offset,
                                bf16* __restrict__ oh, bf16* __restrict__ ol)
{
    const int t = blockIdx.x;
    const float* xr = x + (size_t)t * D_;
    const int base = threadIdx.x * 16;
    __shared__ float red[256];

    float v[16];
#pragma unroll
    for (int i = 0; i < 16; i += 4)
        *reinterpret_cast<float4*>(v + i) =
            *reinterpret_cast<const float4*>(xr + base + i);

    float s = 0.f;
#pragma unroll
    for (int i = 0; i < 16; i++) s += v[i];
    red[threadIdx.x] = s; __syncthreads();
    for (int o = 128; o > 0; o >>= 1) {
        if (threadIdx.x < o) red[threadIdx.x] += red[threadIdx.x + o];
        __syncthreads();
    }
    const float mean = red[0] * (1.0f / D_);
    __syncthreads();

    float vv = 0.f;
#pragma unroll
    for (int i = 0; i < 16; i++) { float d = v[i] - mean; vv += d * d; }
    red[threadIdx.x] = vv; __syncthreads();
    for (int o = 128; o > 0; o >>= 1) {
        if (threadIdx.x < o) red[threadIdx.x] += red[threadIdx.x + o];
        __syncthreads();
    }
    const float rstd = rsqrtf(red[0] * (1.0f / D_) + 1e-5f);

    bf16* ohr = oh + (size_t)t * D_ + base;
    bf16* olr = ol + (size_t)t * D_ + base;
#pragma unroll
    for (int i = 0; i < 16; i += 2) {
        float y0 = (v[i]     - mean) * rstd * scale[base + i]     + offset[base + i];
        float y1 = (v[i + 1] - mean) * rstd * scale[base + i + 1] + offset[base + i + 1];
        uint32_t hi, lo;
        split2(y0, y1, hi, lo);
        *reinterpret_cast<uint32_t*>(ohr + i) = hi;
        *reinterpret_cast<uint32_t*>(olr + i) = lo;
    }
}

// ---------------- RoPE + split (q, k) ----------------------------------------
__global__ void rope_split_kernel(const float* __restrict__ q,
                                  const float* __restrict__ k,
                                  bf16* __restrict__ qh, bf16* __restrict__ ql,
                                  bf16* __restrict__ kh, bf16* __restrict__ kl)
{
    const int t = blockIdx.x;
    const int d0 = threadIdx.x * 16;
    const size_t rb = (size_t)t * D_ + d0;

#pragma unroll
    for (int j = 0; j < 8; j++) {
        const int d = d0 + 2 * j;
        float2 qv = *reinterpret_cast<const float2*>(q + rb + 2 * j);
        float2 kv = *reinterpret_cast<const float2*>(k + rb + 2 * j);
        const int dd = d & (DH_ - 1);
        if (dd < RR_) {
            const int i = dd >> 1;
            const double inv = pow(10000.0, -2.0 * (double)i / (double)RR_);
            const double ang = (double)t * inv;
            const float c = (float)cos(ang);
            const float s = (float)sin(ang);
            float q0 = qv.x, q1 = qv.y;
            qv.x = q0 * c - q1 * s; qv.y = q1 * c + q0 * s;
            float k0 = kv.x, k1 = kv.y;
            kv.x = k0 * c - k1 * s; kv.y = k1 * c + k0 * s;
        }
        uint32_t hi, lo;
        split2(qv.x, qv.y, hi, lo);
        *reinterpret_cast<uint32_t*>(qh + rb + 2 * j) = hi;
        *reinterpret_cast<uint32_t*>(ql + rb + 2 * j) = lo;
        split2(kv.x, kv.y, hi, lo);
        *reinterpret_cast<uint32_t*>(kh + rb + 2 * j) = hi;
        *reinterpret_cast<uint32_t*>(kl + rb + 2 * j) = lo;
    }
}

// ---------------- softmax -> split bf16 --------------------------------------
__global__ void softmax_split_kernel(const float* __restrict__ scores,
                                     bf16* __restrict__ ph, bf16* __restrict__ pl)
{
    const size_t row = blockIdx.x;
    const float* r = scores + row * (size_t)T_;
    const int base = threadIdx.x * 8;
    __shared__ float red[256];

    float v[8];
#pragma unroll
    for (int i = 0; i < 8; i += 4)
        *reinterpret_cast<float4*>(v + i) =
            *reinterpret_cast<const float4*>(r + base + i);

    float m = -1e30f;
#pragma unroll
    for (int i = 0; i < 8; i++) m = fmaxf(m, v[i]);
    red[threadIdx.x] = m; __syncthreads();
    for (int o = 128; o > 0; o >>= 1) {
        if (threadIdx.x < o) red[threadIdx.x] = fmaxf(red[threadIdx.x], red[threadIdx.x + o]);
        __syncthreads();
    }
    m = red[0]; __syncthreads();

    float s = 0.f;
#pragma unroll
    for (int i = 0; i < 8; i++) { v[i] = __expf(v[i] - m); s += v[i]; }
    red[threadIdx.x] = s; __syncthreads();
    for (int o = 128; o > 0; o >>= 1) {
        if (threadIdx.x < o) red[threadIdx.x] += red[threadIdx.x + o];
        __syncthreads();
    }
    const float invs = 1.0f / red[0];

    bf16* phr = ph + row * (size_t)T_ + base;
    bf16* plr = pl + row * (size_t)T_ + base;
#pragma unroll
    for (int i = 0; i < 8; i += 2) {
        uint32_t hi, lo;
        split2(v[i] * invs, v[i + 1] * invs, hi, lo);
        *reinterpret_cast<uint32_t*>(phr + i) = hi;
        *reinterpret_cast<uint32_t*>(plr + i) = lo;
    }
}

// ---------------- transpose + split: in[R][C] fp32 -> out[C][R] bf16 hi/lo ---
__global__ void transpose_split_kernel(const float* __restrict__ in,
                                       bf16* __restrict__ oh, bf16* __restrict__ ol,
                                       int R, int C)
{
    __shared__ float t[32][33];
    const int c0 = blockIdx.x * 32, r0 = blockIdx.y * 32;
    const int x = threadIdx.x, y = threadIdx.y;
#pragma unroll
    for (int i = 0; i < 32; i += 8)
        t[y + i][x] = in[(size_t)(r0 + y + i) * C + c0 + x];
    __syncthreads();
#pragma unroll
    for (int i = 0; i < 32; i += 8) {
        const float vv = t[x][y + i];
        bf16 h = __float2bfloat16_rn(vv);
        bf16 l = __float2bfloat16_rn(vv - __bfloat162float(h));
        const size_t o = (size_t)(c0 + y + i) * R + r0 + x;
        oh[o] = h; ol[o] = l;
    }
}

// per-head transpose+split of V: vt[h][d][t] = v[t][h*DH + d]
__global__ void transpose_v_split_kernel(const float* __restrict__ v,
                                         bf16* __restrict__ oh, bf16* __restrict__ ol)
{
    __shared__ float s[32][33];
    const int h = blockIdx.z;
    const int d0 = blockIdx.x * 32, t0 = blockIdx.y * 32;
    const int x = threadIdx.x, y = threadIdx.y;
#pragma unroll
    for (int i = 0; i < 32; i += 8)
        s[y + i][x] = v[(size_t)(t0 + y + i) * D_ + (size_t)h * DH_ + d0 + x];
    __syncthreads();
#pragma unroll
    for (int i = 0; i < 32; i += 8) {
        const float vv = s[x][y + i];
        bf16 hh = __float2bfloat16_rn(vv);
        bf16 ll = __float2bfloat16_rn(vv - __bfloat162float(hh));
        const size_t o = ((size_t)h * DH_ + d0 + y + i) * T_ + t0 + x;
        oh[o] = hh; ol[o] = ll;
    }
}

// ---------------- split-bf16 mma.sync GEMM (cp.async pipelined) ---------------
// C[z][m][n] = alpha * sum_k (Ah+Al)[z][m][k] * (Bh+Bl)[z][n][k]  (3 products)
enum { E_F32 = 0, E_CAUSAL = 1, E_SPLIT = 2, E_GELU_SPLIT = 3, E_BIASRES = 4 };

__global__ void __launch_bounds__(256, 1)
mma_gemm(int K,
         const bf16* __restrict__ Ah, const bf16* __restrict__ Al,
         int lda, long long sA,
         const bf16* __restrict__ Bh, const bf16* __restrict__ Bl,
         int ldb, long long sB,
         float* __restrict__ C, bf16* __restrict__ Chi, bf16* __restrict__ Clo,
         int ldc, long long sC,
         float alpha, int epi,
         const float* __restrict__ bias,
         const float* __restrict__ res, int ldres)
{
    extern __shared__ char smem[];
    const uint32_t sbase = smem_u32(smem);
    const int tid = threadIdx.x;
    const int wid = tid >> 5, lid = tid & 31;
    const int m0 = blockIdx.y * MT, n0 = blockIdx.x * NTT;

    Ah += (size_t)blockIdx.z * sA;
    Al += (size_t)blockIdx.z * sA;
    Bh += (size_t)blockIdx.z * sB;
    Bl += (size_t)blockIdx.z * sB;
    if (C)   C   += (size_t)blockIdx.z * sC;
    if (Chi) { Chi += (size_t)blockIdx.z * sC; Clo += (size_t)blockIdx.z * sC; }

    // fully-masked causal tile: write mask, skip compute
    if (epi == E_CAUSAL && n0 > m0 + (MT - 1)) {
        for (int idx = tid * 4; idx < MT * NTT; idx += 256 * 4) {
            const int r = idx / NTT, cc = idx % NTT;
            float4 mv = make_float4(-1e10f, -1e10f, -1e10f, -1e10f);
            *reinterpret_cast<float4*>(C + (size_t)(m0 + r) * ldc + n0 + cc) = mv;
        }
        return;
    }

    const int wm = (wid >> 2) * 64;
    const int wn = (wid & 3) * 32;

    float acc[4][4][4];
#pragma unroll
    for (int i = 0; i < 4; i++)
#pragma unroll
        for (int j = 0; j < 4; j++)
#pragma unroll
            for (int r = 0; r < 4; r++) acc[i][j][r] = 0.f;

    // cp.async chunk assignment: 4096 16B-chunks/stage over 256 threads
    const int lrow = tid >> 3;     // 0..31 (plus p*32)
    const int lcol = tid & 7;      // 16B column within 128B row

    const int NC = K / KC;

    // -------- stage issue (macro-ish lambda via plain code) --------
#define ISSUE_STAGE(stg, kc_) do {                                              \
        const int kc__ = (kc_);                                                 \
        _Pragma("unroll")                                                       \
        for (int p = 0; p < 4; p++) {                                           \
            const int row = lrow + p * 32;                                      \
            const uint32_t dsw = SWZ((uint32_t)(row * 128 + lcol * 16));        \
            const uint32_t db = sbase + (uint32_t)(stg) * STAGE_B + dsw;        \
            CP16(db,          Ah + (size_t)(m0 + row) * lda + kc__ + lcol * 8); \
            CP16(db + 16384u, Al + (size_t)(m0 + row) * lda + kc__ + lcol * 8); \
            CP16(db + 32768u, Bh + (size_t)(n0 + row) * ldb + kc__ + lcol * 8); \
            CP16(db + 49152u, Bl + (size_t)(n0 + row) * ldb + kc__ + lcol * 8); \
        }                                                                       \
        CPCOMMIT();                                                             \
    } while (0)

    ISSUE_STAGE(0, 0);
    ISSUE_STAGE(1, KC);

    const uint32_t aRawBase = (uint32_t)((wm + (lid & 15)) * 128 + (lid >> 4) * 16);
    const uint32_t bRawBase = (uint32_t)((wn + (lid & 7) + ((lid >> 4) << 3)) * 128
                                         + (((lid >> 3) & 1) << 4));

    for (int c = 0; c < NC; ++c) {
        if (c + 2 < NC) {
            ISSUE_STAGE((c + 2) % NSTAGE, (c + 2) * KC);
            CPWAIT(2);
        } else {
            CPWAIT(0);
        }
        __syncthreads();

        const uint32_t st = sbase + (uint32_t)(c % NSTAGE) * STAGE_B;

#pragma unroll
        for (int ks = 0; ks < 4; ks++) {
            const uint32_t kb = (uint32_t)ks * 32;
            uint32_t ah[4][4], al[4][4], bh[4][2], bl[4][2];
#pragma unroll
            for (int i = 0; i < 4; i++) {
                const uint32_t raw = aRawBase + (uint32_t)i * (16 * 128) + kb;
                ldm_x4(ah[i], st + SWZ(raw));
                ldm_x4(al[i], st + 16384u + SWZ(raw));
            }
#pragma unroll
            for (int j2 = 0; j2 < 2; j2++) {
                const uint32_t raw = bRawBase + (uint32_t)j2 * (16 * 128) + kb;
                uint32_t t4[4];
                ldm_x4(t4, st + 32768u + SWZ(raw));
                bh[2 * j2][0] = t4[0]; bh[2 * j2][1] = t4[1];
                bh[2 * j2 + 1][0] = t4[2]; bh[2 * j2 + 1][1] = t4[3];
                ldm_x4(t4, st + 49152u + SWZ(raw));
                bl[2 * j2][0] = t4[0]; bl[2 * j2][1] = t4[1];
                bl[2 * j2 + 1][0] = t4[2]; bl[2 * j2 + 1][1] = t4[3];
            }
#pragma unroll
            for (int i = 0; i < 4; i++)
#pragma unroll
                for (int j = 0; j < 4; j++) {
                    mma16816(acc[i][j], ah[i], bh[j]);
                    mma16816(acc[i][j], ah[i], bl[j]);
                    mma16816(acc[i][j], al[i], bh[j]);
                }
        }
        __syncthreads();
    }
#undef ISSUE_STAGE

    // ---------------- epilogue ----------------
    const int tr = lid >> 2, tc = (lid & 3) * 2;
#pragma unroll
    for (int i = 0; i < 4; i++) {
        const int m1 = m0 + wm + i * 16 + tr;
        const int m2 = m1 + 8;
#pragma unroll
        for (int j = 0; j < 4; j++) {
            const int n = n0 + wn + j * 8 + tc;
            float v0 = acc[i][j][0] * alpha;
            float v1 = acc[i][j][1] * alpha;
            float v2 = acc[i][j][2] * alpha;
            float v3 = acc[i][j][3] * alpha;
            if (epi == E_CAUSAL) {
                if (n     > m1) v0 = -1e10f;
                if (n + 1 > m1) v1 = -1e10f;
                if (n     > m2) v2 = -1e10f;
                if (n + 1 > m2) v3 = -1e10f;
            } else if (epi == E_GELU_SPLIT) {
                const float b0 = bias[n], b1 = bias[n + 1];
                v0 = gelu_f(v0 + b0); v1 = gelu_f(v1 + b1);
                v2 = gelu_f(v2 + b0); v3 = gelu_f(v3 + b1);
            } else if (epi == E_BIASRES) {
                const float b0 = bias[n], b1 = bias[n + 1];
                const float2 r1 = *reinterpret_cast<const float2*>(res + (size_t)m1 * ldres + n);
                const float2 r2 = *reinterpret_cast<const float2*>(res + (size_t)m2 * ldres + n);
                v0 += b0 + r1.x; v1 += b1 + r1.y;
                v2 += b0 + r2.x; v3 += b1 + r2.y;
            }
            if (epi == E_SPLIT || epi == E_GELU_SPLIT) {
                uint32_t hi, lo;
                split2(v0, v1, hi, lo);
                *reinterpret_cast<uint32_t*>(Chi + (size_t)m1 * ldc + n) = hi;
                *reinterpret_cast<uint32_t*>(Clo + (size_t)m1 * ldc + n) = lo;
                split2(v2, v3, hi, lo);
                *reinterpret_cast<uint32_t*>(Chi + (size_t)m2 * ldc + n) = hi;
                *reinterpret_cast<uint32_t*>(Clo + (size_t)m2 * ldc + n) = lo;
            } else {
                *reinterpret_cast<float2*>(C + (size_t)m1 * ldc + n) = make_float2(v0, v1);
                *reinterpret_cast<float2*>(C + (size_t)m2 * ldc + n) = make_float2(v2, v3);
            }
        }
    }
}

// ---------------- launch -----------------------------------------------------
extern "C" void kernel_launch(void* const* d_in, const int* in_sizes, int n_in,
                              void* d_out, int out_size)
{
    const float* x    = (const float*)d_in[0];
    const float* ln_s = (const float*)d_in[1];
    const float* ln_o = (const float*)d_in[2];
    const float* wq   = (const float*)d_in[3];
    const float* wk   = (const float*)d_in[4];
    const float* wv   = (const float*)d_in[5];
    const float* wo   = (const float*)d_in[6];
    const float* w1   = (const float*)d_in[7];
    const float* b1   = (const float*)d_in[8];
    const float* w2   = (const float*)d_in[9];
    const float* b2   = (const float*)d_in[10];
    float* out = (float*)d_out;

    float *q, *k, *v, *attn, *sc;
    bf16 *xnh, *xnl, *qh, *ql, *kh, *kl, *vth, *vtl, *sch, *scl;
    bf16 *cxh, *cxl, *hbh, *hbl;
    bf16 *wqh, *wql, *wkh, *wkl, *wvh, *wvl, *woh, *wol, *w1h, *w1l, *w2h, *w2l;

    cudaGetSymbolAddress((void**)&q,    g_q);
    cudaGetSymbolAddress((void**)&k,    g_k);
    cudaGetSymbolAddress((void**)&v,    g_v);
    cudaGetSymbolAddress((void**)&attn, g_attn);
    cudaGetSymbolAddress((void**)&sc,   g_sc);
    cudaGetSymbolAddress((void**)&xnh,  g_xnh);
    cudaGetSymbolAddress((void**)&xnl,  g_xnl);
    cudaGetSymbolAddress((void**)&qh,   g_qh);
    cudaGetSymbolAddress((void**)&ql,   g_ql);
    cudaGetSymbolAddress((void**)&kh,   g_kh);
    cudaGetSymbolAddress((void**)&kl,   g_kl);
    cudaGetSymbolAddress((void**)&vth,  g_vth);
    cudaGetSymbolAddress((void**)&vtl,  g_vtl);
    cudaGetSymbolAddress((void**)&sch,  g_sch);
    cudaGetSymbolAddress((void**)&scl,  g_scl);
    cudaGetSymbolAddress((void**)&cxh,  g_cxh);
    cudaGetSymbolAddress((void**)&cxl,  g_cxl);
    cudaGetSymbolAddress((void**)&hbh,  g_hbh);
    cudaGetSymbolAddress((void**)&hbl,  g_hbl);
    cudaGetSymbolAddress((void**)&wqh,  g_wqh);
    cudaGetSymbolAddress((void**)&wql,  g_wql);
    cudaGetSymbolAddress((void**)&wkh,  g_wkh);
    cudaGetSymbolAddress((void**)&wkl,  g_wkl);
    cudaGetSymbolAddress((void**)&wvh,  g_wvh);
    cudaGetSymbolAddress((void**)&wvl,  g_wvl);
    cudaGetSymbolAddress((void**)&woh,  g_woh);
    cudaGetSymbolAddress((void**)&wol,  g_wol);
    cudaGetSymbolAddress((void**)&w1h,  g_w1h);
    cudaGetSymbolAddress((void**)&w1l,  g_w1l);
    cudaGetSymbolAddress((void**)&w2h,  g_w2h);
    cudaGetSymbolAddress((void**)&w2l,  g_w2l);

    cudaFuncSetAttribute(mma_gemm, cudaFuncAttributeMaxDynamicSharedMemorySize,
                         GEMM_SMEM_BYTES);

    const dim3 tb32(32, 8);

    // 0) weight transpose+split: W[k][n] -> WT hi/lo [n][k]
    transpose_split_kernel<<<dim3(D_ / 32, D_ / 32), tb32>>>(wq, wqh, wql, D_, D_);
    transpose_split_kernel<<<dim3(D_ / 32, D_ / 32), tb32>>>(wk, wkh, wkl, D_, D_);
    transpose_split_kernel<<<dim3(D_ / 32, D_ / 32), tb32>>>(wv, wvh, wvl, D_, D_);
    transpose_split_kernel<<<dim3(D_ / 32, D_ / 32), tb32>>>(wo, woh, wol, D_, D_);
    transpose_split_kernel<<<dim3(FF_ / 32, D_ / 32), tb32>>>(w1, w1h, w1l, D_, FF_);
    transpose_split_kernel<<<dim3(D_ / 32, FF_ / 32), tb32>>>(w2, w2h, w2l, FF_, D_);

    // 1) LayerNorm -> xn hi/lo
    ln_split_kernel<<<T_, 256>>>(x, ln_s, ln_o, xnh, xnl);

    // 2) Q/K/V projections (fp32 out)
    {
        dim3 g(D_ / NTT, T_ / MT, 1);
        mma_gemm<<<g, 256, GEMM_SMEM_BYTES>>>(D_, xnh, xnl, D_, 0, wqh, wql, D_, 0,
            q, nullptr, nullptr, D_, 0, 1.f, E_F32, nullptr, nullptr, 0);
        mma_gemm<<<g, 256, GEMM_SMEM_BYTES>>>(D_, xnh, xnl, D_, 0, wkh, wkl, D_, 0,
            k, nullptr, nullptr, D_, 0, 1.f, E_F32, nullptr, nullptr, 0);
        mma_gemm<<<g, 256, GEMM_SMEM_BYTES>>>(D_, xnh, xnl, D_, 0, wvh, wvl, D_, 0,
            v, nullptr, nullptr, D_, 0, 1.f, E_F32, nullptr, nullptr, 0);
    }

    // 3) RoPE + split q,k
    rope_split_kernel<<<T_, 256>>>(q, k, qh, ql, kh, kl);

    // 4) V transpose + split
    transpose_v_split_kernel<<<dim3(DH_ / 32, T_ / 32, H_), tb32>>>(v, vth, vtl);

    // 5) scores = scale * Q_h @ K_h^T + causal (fp32)
    {
        dim3 g(T_ / NTT, T_ / MT, H_);
        mma_gemm<<<g, 256, GEMM_SMEM_BYTES>>>(DH_,
            qh, ql, D_, DH_,
            kh, kl, D_, DH_,
            sc, nullptr, nullptr, T_, (long long)T_ * T_,
            0.0625f, E_CAUSAL, nullptr, nullptr, 0);
    }

    // 6) softmax -> P hi/lo
    softmax_split_kernel<<<H_ * T_, 256>>>(sc, sch, scl);

    // 7) ctx = P_h @ V_h  (split out)
    {
        dim3 g(DH_ / NTT, T_ / MT, H_);
        mma_gemm<<<g, 256, GEMM_SMEM_BYTES>>>(T_,
            sch, scl, T_, (long long)T_ * T_,
            vth, vtl, T_, (long long)DH_ * T_,
            nullptr, cxh, cxl, D_, DH_,
            1.f, E_SPLIT, nullptr, nullptr, 0);
    }

    // 8) attn_out = ctx @ wo (fp32)
    {
        dim3 g(D_ / NTT, T_ / MT, 1);
        mma_gemm<<<g, 256, GEMM_SMEM_BYTES>>>(D_, cxh, cxl, D_, 0, woh, wol, D_, 0,
            attn, nullptr, nullptr, D_, 0, 1.f, E_F32, nullptr, nullptr, 0);
    }

    // 9) h = gelu(xn @ w1 + b1)  (split out)
    {
        dim3 g(FF_ / NTT, T_ / MT, 1);
        mma_gemm<<<g, 256, GEMM_SMEM_BYTES>>>(D_, xnh, xnl, D_, 0, w1h, w1l, D_, 0,
            nullptr, hbh, hbl, FF_, 0, 1.f, E_GELU_SPLIT, b1, nullptr, 0);
    }

    // 10) out = h @ w2 + b2 + attn_out
    {
        dim3 g(D_ / NTT, T_ / MT, 1);
        mma_gemm<<<g, 256, GEMM_SMEM_BYTES>>>(FF_, hbh, hbl, FF_, 0, w2h, w2l, FF_, 0,
            out, nullptr, nullptr, D_, 0, 1.f, E_BIASRES, b2, attn, D_);
    }
}